// round 1
// baseline (speedup 1.0000x reference)
#include <cuda_runtime.h>
#include <math.h>

// Problem constants
#define BATCH 8
#define SEQ   2048
#define EMB   1024
#define HD    128
#define MROWS (BATCH*SEQ)   // 16384

// Attention tiling
#define BQ 64
#define BK 64
#define PADK 68   // Kt row stride (64 cols + 4 pad)
#define PADP 68   // Ps row stride

// Dynamic smem layout (floats): Qs[64*128] | Kt[128*68] | Vs[64*128] | Ps[64*68]
#define OFF_QS 0
#define OFF_KT 8192
#define OFF_VS 16896
#define OFF_PS 25088
#define SMEM_FLOATS 29440
#define SMEM_BYTES (SMEM_FLOATS*4)

// Scratch for projected q,k,v  (8 MB each, static device arrays: allowed)
__device__ float g_q[MROWS*HD];
__device__ float g_k[MROWS*HD];
__device__ float g_v[MROWS*HD];

// ---------------------------------------------------------------------------
// Kernel 1: fused QKV projection.  out[row][n] = sum_k x[row][k] * W[k][n]
// grid = (MROWS/64, 3), block = 256.  blockIdx.y selects (q,k,v).
// ---------------------------------------------------------------------------
__global__ __launch_bounds__(256) void qkv_proj_kernel(
    const float* __restrict__ x,
    const float* __restrict__ Wk,
    const float* __restrict__ Wq,
    const float* __restrict__ Wv)
{
    __shared__ float xs[64*36];    // 64 rows x 32 k, padded stride 36
    __shared__ float ws[32*128];   // 32 k x 128 n

    const int t  = threadIdx.x;
    const int ty = t >> 4;   // 0..15 -> row group
    const int tx = t & 15;   // 0..15 -> col group
    const int rowBase = blockIdx.x * 64;

    const float* W;
    float* outp;
    if (blockIdx.y == 0)      { W = Wq; outp = g_q; }
    else if (blockIdx.y == 1) { W = Wk; outp = g_k; }
    else                      { W = Wv; outp = g_v; }

    float acc[4][8];
    #pragma unroll
    for (int i = 0; i < 4; i++)
        #pragma unroll
        for (int j = 0; j < 8; j++) acc[i][j] = 0.f;

    for (int k0 = 0; k0 < EMB; k0 += 32) {
        // load x tile: 64 rows x 32 k  (512 float4 / 256 threads = 2 each)
        #pragma unroll
        for (int l = 0; l < 2; l++) {
            int idx = t + l*256;
            int r  = idx >> 3;
            int kv = idx & 7;
            float4 vx = *(const float4*)(x + (size_t)(rowBase + r)*EMB + k0 + kv*4);
            *(float4*)(xs + r*36 + kv*4) = vx;
        }
        // load W tile: 32 k x 128 n  (1024 float4 / 256 = 4 each)
        #pragma unroll
        for (int l = 0; l < 4; l++) {
            int idx = t + l*256;
            int kk = idx >> 5;
            int nv = idx & 31;
            float4 vw = *(const float4*)(W + (size_t)(k0 + kk)*HD + nv*4);
            *(float4*)(ws + kk*128 + nv*4) = vw;
        }
        __syncthreads();

        #pragma unroll
        for (int k = 0; k < 32; k++) {
            float a[4];
            #pragma unroll
            for (int i = 0; i < 4; i++) a[i] = xs[(ty*4 + i)*36 + k];
            float w0[4], w1[4];
            *(float4*)w0 = *(const float4*)(ws + k*128 + tx*4);
            *(float4*)w1 = *(const float4*)(ws + k*128 + 64 + tx*4);
            #pragma unroll
            for (int i = 0; i < 4; i++) {
                #pragma unroll
                for (int j = 0; j < 4; j++) {
                    acc[i][j]     = fmaf(a[i], w0[j], acc[i][j]);
                    acc[i][4 + j] = fmaf(a[i], w1[j], acc[i][4 + j]);
                }
            }
        }
        __syncthreads();
    }

    #pragma unroll
    for (int i = 0; i < 4; i++) {
        size_t r = (size_t)(rowBase + ty*4 + i);
        *(float4*)(outp + r*HD + tx*4)      = make_float4(acc[i][0], acc[i][1], acc[i][2], acc[i][3]);
        *(float4*)(outp + r*HD + 64 + tx*4) = make_float4(acc[i][4], acc[i][5], acc[i][6], acc[i][7]);
    }
}

// ---------------------------------------------------------------------------
// Kernel 2: causal flash attention, fp32, online softmax.
// grid = BATCH * (SEQ/BQ) = 256 blocks (heavy tiles scheduled first),
// block = 256 threads (16x16), dynamic smem = SMEM_BYTES.
// ---------------------------------------------------------------------------
__global__ __launch_bounds__(256) void attn_kernel(float* __restrict__ out)
{
    extern __shared__ float smem[];
    float* Qs = smem + OFF_QS;   // [64][128]
    float* Kt = smem + OFF_KT;   // [128][68]  (transposed K)
    float* Vs = smem + OFF_VS;   // [64][128]
    float* Ps = smem + OFF_PS;   // [64][68]

    const int l  = blockIdx.x;
    const int b  = l & 7;
    const int qt = (SEQ/BQ - 1) - (l >> 3);   // heavy (late) query tiles first
    const int qbase = qt * BQ;

    const int t  = threadIdx.x;
    const int ty = t >> 4;
    const int tx = t & 15;

    const float* Qg = g_q + ((size_t)b*SEQ)*HD;
    const float* Kg = g_k + ((size_t)b*SEQ)*HD;
    const float* Vg = g_v + ((size_t)b*SEQ)*HD;

    // load Q tile (2048 float4 / 256 = 8 each)
    #pragma unroll
    for (int l2 = 0; l2 < 8; l2++) {
        int idx = t + l2*256;
        int r  = idx >> 5;
        int dv = idx & 31;
        *(float4*)(Qs + r*128 + dv*4) =
            *(const float4*)(Qg + (size_t)(qbase + r)*HD + dv*4);
    }

    float o[4][8];
    #pragma unroll
    for (int i = 0; i < 4; i++)
        #pragma unroll
        for (int j = 0; j < 8; j++) o[i][j] = 0.f;
    float m_i[4] = {-1e30f, -1e30f, -1e30f, -1e30f};
    float l_i[4] = {0.f, 0.f, 0.f, 0.f};

    const float scale = 0.08838834764831845f;  // 128^-0.5

    for (int kt = 0; kt <= qt; kt++) {
        const int kbase = kt * BK;
        __syncthreads();   // protect Kt/Vs/Ps from readers of previous iter (and Qs on iter 0)

        // load K (transposed into Kt) and V (row-major)
        #pragma unroll
        for (int l2 = 0; l2 < 8; l2++) {
            int idx = t + l2*256;
            int c  = idx >> 5;
            int dv = idx & 31;
            float4 kvv = *(const float4*)(Kg + (size_t)(kbase + c)*HD + dv*4);
            Kt[(dv*4 + 0)*PADK + c] = kvv.x;
            Kt[(dv*4 + 1)*PADK + c] = kvv.y;
            Kt[(dv*4 + 2)*PADK + c] = kvv.z;
            Kt[(dv*4 + 3)*PADK + c] = kvv.w;
            *(float4*)(Vs + c*128 + dv*4) =
                *(const float4*)(Vg + (size_t)(kbase + c)*HD + dv*4);
        }
        __syncthreads();

        // S = Q @ K^T   (4x4 per thread)
        float s[4][4];
        #pragma unroll
        for (int i = 0; i < 4; i++)
            #pragma unroll
            for (int j = 0; j < 4; j++) s[i][j] = 0.f;

        for (int d = 0; d < 128; d += 4) {
            float qc[4][4], kc[4][4];
            #pragma unroll
            for (int i = 0; i < 4; i++)
                *(float4*)qc[i] = *(const float4*)(Qs + (ty*4 + i)*128 + d);
            #pragma unroll
            for (int dd = 0; dd < 4; dd++)
                *(float4*)kc[dd] = *(const float4*)(Kt + (d + dd)*PADK + tx*4);
            #pragma unroll
            for (int i = 0; i < 4; i++)
                #pragma unroll
                for (int j = 0; j < 4; j++) {
                    s[i][j] = fmaf(qc[i][0], kc[0][j], s[i][j]);
                    s[i][j] = fmaf(qc[i][1], kc[1][j], s[i][j]);
                    s[i][j] = fmaf(qc[i][2], kc[2][j], s[i][j]);
                    s[i][j] = fmaf(qc[i][3], kc[3][j], s[i][j]);
                }
        }

        // scale + causal mask (only the diagonal tile needs masking)
        #pragma unroll
        for (int i = 0; i < 4; i++)
            #pragma unroll
            for (int j = 0; j < 4; j++) {
                s[i][j] *= scale;
                if (kt == qt) {
                    if ((kbase + tx*4 + j) > (qbase + ty*4 + i)) s[i][j] = -1e30f;
                }
            }

        // online softmax: reduce across the 16 lanes sharing a row group
        #pragma unroll
        for (int i = 0; i < 4; i++) {
            float mloc = fmaxf(fmaxf(s[i][0], s[i][1]), fmaxf(s[i][2], s[i][3]));
            #pragma unroll
            for (int off = 8; off >= 1; off >>= 1)
                mloc = fmaxf(mloc, __shfl_xor_sync(0xffffffffu, mloc, off));
            float mnew  = fmaxf(m_i[i], mloc);
            float alpha = __expf(m_i[i] - mnew);
            float p0 = __expf(s[i][0] - mnew);
            float p1 = __expf(s[i][1] - mnew);
            float p2 = __expf(s[i][2] - mnew);
            float p3 = __expf(s[i][3] - mnew);
            float rsum = p0 + p1 + p2 + p3;
            #pragma unroll
            for (int off = 8; off >= 1; off >>= 1)
                rsum += __shfl_xor_sync(0xffffffffu, rsum, off);
            l_i[i] = l_i[i]*alpha + rsum;
            m_i[i] = mnew;
            #pragma unroll
            for (int j = 0; j < 8; j++) o[i][j] *= alpha;
            *(float4*)(Ps + (ty*4 + i)*PADP + tx*4) = make_float4(p0, p1, p2, p3);
        }
        __syncthreads();

        // O += P @ V
        for (int c = 0; c < 64; c += 4) {
            float pc[4][4];
            #pragma unroll
            for (int i = 0; i < 4; i++)
                *(float4*)pc[i] = *(const float4*)(Ps + (ty*4 + i)*PADP + c);
            #pragma unroll
            for (int cc = 0; cc < 4; cc++) {
                float vc0[4], vc1[4];
                *(float4*)vc0 = *(const float4*)(Vs + (c + cc)*128 + tx*4);
                *(float4*)vc1 = *(const float4*)(Vs + (c + cc)*128 + 64 + tx*4);
                #pragma unroll
                for (int i = 0; i < 4; i++) {
                    float p = pc[i][cc];
                    #pragma unroll
                    for (int j = 0; j < 4; j++) {
                        o[i][j]     = fmaf(p, vc0[j], o[i][j]);
                        o[i][4 + j] = fmaf(p, vc1[j], o[i][4 + j]);
                    }
                }
            }
        }
    }

    // epilogue: normalize and write out
    float* Ob = out + ((size_t)b*SEQ + qbase)*HD;
    #pragma unroll
    for (int i = 0; i < 4; i++) {
        float inv = 1.f / l_i[i];
        size_t r = (size_t)(ty*4 + i);
        *(float4*)(Ob + r*HD + tx*4) =
            make_float4(o[i][0]*inv, o[i][1]*inv, o[i][2]*inv, o[i][3]*inv);
        *(float4*)(Ob + r*HD + 64 + tx*4) =
            make_float4(o[i][4]*inv, o[i][5]*inv, o[i][6]*inv, o[i][7]*inv);
    }
}

// ---------------------------------------------------------------------------
extern "C" void kernel_launch(void* const* d_in, const int* in_sizes, int n_in,
                              void* d_out, int out_size)
{
    const float* x  = (const float*)d_in[0];
    const float* Wk = (const float*)d_in[1];
    const float* Wq = (const float*)d_in[2];
    const float* Wv = (const float*)d_in[3];
    float* out = (float*)d_out;

    dim3 g1(MROWS/64, 3);
    qkv_proj_kernel<<<g1, 256>>>(x, Wk, Wq, Wv);

    cudaFuncSetAttribute(attn_kernel,
                         cudaFuncAttributeMaxDynamicSharedMemorySize, SMEM_BYTES);
    attn_kernel<<<BATCH*(SEQ/BQ), 256, SMEM_BYTES>>>(out);
}

// round 2
// speedup vs baseline: 1.0003x; 1.0003x over previous
#include <cuda_runtime.h>
#include <math.h>

// Problem constants
#define BATCH 8
#define SEQ   2048
#define EMB   1024
#define HD    128
#define MROWS (BATCH*SEQ)   // 16384

// Attention tiling
#define BQ 64
#define BK 64
#define PADK 68   // Kt row stride (64 cols + 4 pad)
#define PADP 68   // Ps row stride

// Dynamic smem layout (floats): Qs[64*128] | Kt[128*68] | Vs[64*128] | Ps[64*68]
#define OFF_QS 0
#define OFF_KT 8192
#define OFF_VS 16896
#define OFF_PS 25088
#define SMEM_FLOATS 29440
#define SMEM_BYTES (SMEM_FLOATS*4)

// Scratch for projected q,k,v  (8 MB each, static device arrays: allowed)
__device__ float g_q[MROWS*HD];
__device__ float g_k[MROWS*HD];
__device__ float g_v[MROWS*HD];

// ---------------------------------------------------------------------------
// Kernel 1: fused QKV projection.  out[row][n] = sum_k x[row][k] * W[k][n]
// grid = (MROWS/64, 3), block = 256.  blockIdx.y selects (q,k,v).
// ---------------------------------------------------------------------------
__global__ __launch_bounds__(256) void qkv_proj_kernel(
    const float* __restrict__ x,
    const float* __restrict__ Wk,
    const float* __restrict__ Wq,
    const float* __restrict__ Wv)
{
    __shared__ float xs[64*36];    // 64 rows x 32 k, padded stride 36
    __shared__ float ws[32*128];   // 32 k x 128 n

    const int t  = threadIdx.x;
    const int ty = t >> 4;   // 0..15 -> row group
    const int tx = t & 15;   // 0..15 -> col group
    const int rowBase = blockIdx.x * 64;

    const float* W;
    float* outp;
    if (blockIdx.y == 0)      { W = Wq; outp = g_q; }
    else if (blockIdx.y == 1) { W = Wk; outp = g_k; }
    else                      { W = Wv; outp = g_v; }

    float acc[4][8];
    #pragma unroll
    for (int i = 0; i < 4; i++)
        #pragma unroll
        for (int j = 0; j < 8; j++) acc[i][j] = 0.f;

    for (int k0 = 0; k0 < EMB; k0 += 32) {
        // load x tile: 64 rows x 32 k  (512 float4 / 256 threads = 2 each)
        #pragma unroll
        for (int l = 0; l < 2; l++) {
            int idx = t + l*256;
            int r  = idx >> 3;
            int kv = idx & 7;
            float4 vx = *(const float4*)(x + (size_t)(rowBase + r)*EMB + k0 + kv*4);
            *(float4*)(xs + r*36 + kv*4) = vx;
        }
        // load W tile: 32 k x 128 n  (1024 float4 / 256 = 4 each)
        #pragma unroll
        for (int l = 0; l < 4; l++) {
            int idx = t + l*256;
            int kk = idx >> 5;
            int nv = idx & 31;
            float4 vw = *(const float4*)(W + (size_t)(k0 + kk)*HD + nv*4);
            *(float4*)(ws + kk*128 + nv*4) = vw;
        }
        __syncthreads();

        #pragma unroll
        for (int k = 0; k < 32; k++) {
            float a[4];
            #pragma unroll
            for (int i = 0; i < 4; i++) a[i] = xs[(ty*4 + i)*36 + k];
            float w0[4], w1[4];
            *(float4*)w0 = *(const float4*)(ws + k*128 + tx*4);
            *(float4*)w1 = *(const float4*)(ws + k*128 + 64 + tx*4);
            #pragma unroll
            for (int i = 0; i < 4; i++) {
                #pragma unroll
                for (int j = 0; j < 4; j++) {
                    acc[i][j]     = fmaf(a[i], w0[j], acc[i][j]);
                    acc[i][4 + j] = fmaf(a[i], w1[j], acc[i][4 + j]);
                }
            }
        }
        __syncthreads();
    }

    #pragma unroll
    for (int i = 0; i < 4; i++) {
        size_t r = (size_t)(rowBase + ty*4 + i);
        *(float4*)(outp + r*HD + tx*4)      = make_float4(acc[i][0], acc[i][1], acc[i][2], acc[i][3]);
        *(float4*)(outp + r*HD + 64 + tx*4) = make_float4(acc[i][4], acc[i][5], acc[i][6], acc[i][7]);
    }
}

// ---------------------------------------------------------------------------
// Kernel 2: causal flash attention, fp32, online softmax.
// grid = BATCH * (SEQ/BQ) = 256 blocks (heavy tiles scheduled first),
// block = 256 threads (16x16), dynamic smem = SMEM_BYTES.
// ---------------------------------------------------------------------------
__global__ __launch_bounds__(256) void attn_kernel(float* __restrict__ out)
{
    extern __shared__ float smem[];
    float* Qs = smem + OFF_QS;   // [64][128]
    float* Kt = smem + OFF_KT;   // [128][68]  (transposed K)
    float* Vs = smem + OFF_VS;   // [64][128]
    float* Ps = smem + OFF_PS;   // [64][68]

    const int l  = blockIdx.x;
    const int b  = l & 7;
    const int qt = (SEQ/BQ - 1) - (l >> 3);   // heavy (late) query tiles first
    const int qbase = qt * BQ;

    const int t  = threadIdx.x;
    const int ty = t >> 4;
    const int tx = t & 15;

    const float* Qg = g_q + ((size_t)b*SEQ)*HD;
    const float* Kg = g_k + ((size_t)b*SEQ)*HD;
    const float* Vg = g_v + ((size_t)b*SEQ)*HD;

    // load Q tile (2048 float4 / 256 = 8 each)
    #pragma unroll
    for (int l2 = 0; l2 < 8; l2++) {
        int idx = t + l2*256;
        int r  = idx >> 5;
        int dv = idx & 31;
        *(float4*)(Qs + r*128 + dv*4) =
            *(const float4*)(Qg + (size_t)(qbase + r)*HD + dv*4);
    }

    float o[4][8];
    #pragma unroll
    for (int i = 0; i < 4; i++)
        #pragma unroll
        for (int j = 0; j < 8; j++) o[i][j] = 0.f;
    float m_i[4] = {-1e30f, -1e30f, -1e30f, -1e30f};
    float l_i[4] = {0.f, 0.f, 0.f, 0.f};

    const float scale = 0.08838834764831845f;  // 128^-0.5

    for (int kt = 0; kt <= qt; kt++) {
        const int kbase = kt * BK;
        __syncthreads();   // protect Kt/Vs/Ps from readers of previous iter (and Qs on iter 0)

        // load K (transposed into Kt) and V (row-major)
        #pragma unroll
        for (int l2 = 0; l2 < 8; l2++) {
            int idx = t + l2*256;
            int c  = idx >> 5;
            int dv = idx & 31;
            float4 kvv = *(const float4*)(Kg + (size_t)(kbase + c)*HD + dv*4);
            Kt[(dv*4 + 0)*PADK + c] = kvv.x;
            Kt[(dv*4 + 1)*PADK + c] = kvv.y;
            Kt[(dv*4 + 2)*PADK + c] = kvv.z;
            Kt[(dv*4 + 3)*PADK + c] = kvv.w;
            *(float4*)(Vs + c*128 + dv*4) =
                *(const float4*)(Vg + (size_t)(kbase + c)*HD + dv*4);
        }
        __syncthreads();

        // S = Q @ K^T   (4x4 per thread)
        float s[4][4];
        #pragma unroll
        for (int i = 0; i < 4; i++)
            #pragma unroll
            for (int j = 0; j < 4; j++) s[i][j] = 0.f;

        for (int d = 0; d < 128; d += 4) {
            float qc[4][4], kc[4][4];
            #pragma unroll
            for (int i = 0; i < 4; i++)
                *(float4*)qc[i] = *(const float4*)(Qs + (ty*4 + i)*128 + d);
            #pragma unroll
            for (int dd = 0; dd < 4; dd++)
                *(float4*)kc[dd] = *(const float4*)(Kt + (d + dd)*PADK + tx*4);
            #pragma unroll
            for (int i = 0; i < 4; i++)
                #pragma unroll
                for (int j = 0; j < 4; j++) {
                    s[i][j] = fmaf(qc[i][0], kc[0][j], s[i][j]);
                    s[i][j] = fmaf(qc[i][1], kc[1][j], s[i][j]);
                    s[i][j] = fmaf(qc[i][2], kc[2][j], s[i][j]);
                    s[i][j] = fmaf(qc[i][3], kc[3][j], s[i][j]);
                }
        }

        // scale + causal mask (only the diagonal tile needs masking)
        #pragma unroll
        for (int i = 0; i < 4; i++)
            #pragma unroll
            for (int j = 0; j < 4; j++) {
                s[i][j] *= scale;
                if (kt == qt) {
                    if ((kbase + tx*4 + j) > (qbase + ty*4 + i)) s[i][j] = -1e30f;
                }
            }

        // online softmax: reduce across the 16 lanes sharing a row group
        #pragma unroll
        for (int i = 0; i < 4; i++) {
            float mloc = fmaxf(fmaxf(s[i][0], s[i][1]), fmaxf(s[i][2], s[i][3]));
            #pragma unroll
            for (int off = 8; off >= 1; off >>= 1)
                mloc = fmaxf(mloc, __shfl_xor_sync(0xffffffffu, mloc, off));
            float mnew  = fmaxf(m_i[i], mloc);
            float alpha = __expf(m_i[i] - mnew);
            float p0 = __expf(s[i][0] - mnew);
            float p1 = __expf(s[i][1] - mnew);
            float p2 = __expf(s[i][2] - mnew);
            float p3 = __expf(s[i][3] - mnew);
            float rsum = p0 + p1 + p2 + p3;
            #pragma unroll
            for (int off = 8; off >= 1; off >>= 1)
                rsum += __shfl_xor_sync(0xffffffffu, rsum, off);
            l_i[i] = l_i[i]*alpha + rsum;
            m_i[i] = mnew;
            #pragma unroll
            for (int j = 0; j < 8; j++) o[i][j] *= alpha;
            *(float4*)(Ps + (ty*4 + i)*PADP + tx*4) = make_float4(p0, p1, p2, p3);
        }
        __syncthreads();

        // O += P @ V
        for (int c = 0; c < 64; c += 4) {
            float pc[4][4];
            #pragma unroll
            for (int i = 0; i < 4; i++)
                *(float4*)pc[i] = *(const float4*)(Ps + (ty*4 + i)*PADP + c);
            #pragma unroll
            for (int cc = 0; cc < 4; cc++) {
                float vc0[4], vc1[4];
                *(float4*)vc0 = *(const float4*)(Vs + (c + cc)*128 + tx*4);
                *(float4*)vc1 = *(const float4*)(Vs + (c + cc)*128 + 64 + tx*4);
                #pragma unroll
                for (int i = 0; i < 4; i++) {
                    float p = pc[i][cc];
                    #pragma unroll
                    for (int j = 0; j < 4; j++) {
                        o[i][j]     = fmaf(p, vc0[j], o[i][j]);
                        o[i][4 + j] = fmaf(p, vc1[j], o[i][4 + j]);
                    }
                }
            }
        }
    }

    // epilogue: normalize and write out
    float* Ob = out + ((size_t)b*SEQ + qbase)*HD;
    #pragma unroll
    for (int i = 0; i < 4; i++) {
        float inv = 1.f / l_i[i];
        size_t r = (size_t)(ty*4 + i);
        *(float4*)(Ob + r*HD + tx*4) =
            make_float4(o[i][0]*inv, o[i][1]*inv, o[i][2]*inv, o[i][3]*inv);
        *(float4*)(Ob + r*HD + 64 + tx*4) =
            make_float4(o[i][4]*inv, o[i][5]*inv, o[i][6]*inv, o[i][7]*inv);
    }
}

// ---------------------------------------------------------------------------
extern "C" void kernel_launch(void* const* d_in, const int* in_sizes, int n_in,
                              void* d_out, int out_size)
{
    const float* x  = (const float*)d_in[0];
    const float* Wk = (const float*)d_in[1];
    const float* Wq = (const float*)d_in[2];
    const float* Wv = (const float*)d_in[3];
    float* out = (float*)d_out;

    dim3 g1(MROWS/64, 3);
    qkv_proj_kernel<<<g1, 256>>>(x, Wk, Wq, Wv);

    cudaFuncSetAttribute(attn_kernel,
                         cudaFuncAttributeMaxDynamicSharedMemorySize, SMEM_BYTES);
    attn_kernel<<<BATCH*(SEQ/BQ), 256, SMEM_BYTES>>>(out);
}